// round 5
// baseline (speedup 1.0000x reference)
#include <cuda_runtime.h>
#include <cstdint>

#define VOCAB   100000
#define NCODES  100000
#define NANC    8
#define EMB     128

// Scratch: projected embeddings P1 = W_emb @ W_att[0:128], P2 = W_emb @ W_att[128:256]
__device__ __align__(16) float g_P1[(size_t)VOCAB * EMB];
__device__ __align__(16) float g_P2[(size_t)VOCAB * EMB];

// Index-dtype flag: 1 if leaves/ancestors buffers are int64, 0 if int32.
__device__ int g_is64;

__device__ __forceinline__ float tanh_fast(float x) {
    float y;
    asm("tanh.approx.f32 %0, %1;" : "=f"(y) : "f"(x));
    return y;
}

// ---------------------------------------------------------------------------
// Dtype detection: genuine int64 indices (values in [0, VOCAB)) have every
// odd 32-bit word == 0. Random int32 indices make that essentially impossible
// across 400k words. Scans only the first NCODES*NANC 32-bit words, which is
// in-bounds for both interpretations. Overwrites g_is64 every call (graph-safe).
// ---------------------------------------------------------------------------
__global__ void detect_kernel(const unsigned int* __restrict__ w) {
    int nz = 0;
    for (int i = threadIdx.x; i < (NCODES * NANC) / 2; i += blockDim.x)
        nz |= (w[2 * i + 1] != 0u);
    nz = __syncthreads_or(nz);
    if (threadIdx.x == 0) g_is64 = (nz == 0);
}

// ---------------------------------------------------------------------------
// Projection GEMM: P[half] = W_emb[VOCAB,128] @ W_att[half*128 .. +128, :]
// BM=64, BN=128 (full), K=128 (full, in smem). 256 threads, f32x2 packed FMA.
// smem: As 64x128 (32KB) + Bs 128x128 (64KB) = 96KB dynamic.
// ---------------------------------------------------------------------------
__global__ __launch_bounds__(256, 2) void proj_kernel(const float* __restrict__ A,
                                                      const float* __restrict__ Watt) {
    extern __shared__ float sm[];
    float (*As)[128] = (float (*)[128])sm;               // [64][128]
    float (*Bs)[128] = (float (*)[128])(sm + 64 * 128);  // [128][128]

    const int half = blockIdx.y;
    const float* W = Watt + half * 128 * 128;
    float* P = half ? g_P2 : g_P1;
    const int m0 = blockIdx.x * 64;
    const int tid = threadIdx.x;

#pragma unroll
    for (int i = 0; i < 16; i++) {
        int idx = (tid + i * 256) * 4;
        *(float4*)((float*)Bs + idx) = __ldg((const float4*)(W + idx));
    }
#pragma unroll
    for (int i = 0; i < 8; i++) {
        int idx = (tid + i * 256) * 4;
        int m = idx >> 7;
        int k = idx & 127;
        int gm = m0 + m;
        if (gm >= VOCAB) gm = VOCAB - 1;
        *(float4*)(&As[m][k]) = __ldg((const float4*)(A + (size_t)gm * EMB + k));
    }
    __syncthreads();

    const int tx = tid & 15;
    const int ty = tid >> 4;
    const int mrow = ty * 4;
    const int ncol = tx * 8;

    unsigned long long acc[4][4];
#pragma unroll
    for (int i = 0; i < 4; i++)
#pragma unroll
        for (int j = 0; j < 4; j++) acc[i][j] = 0ull;

#pragma unroll 4
    for (int k0 = 0; k0 < 128; k0 += 4) {
        float4 av[4];
#pragma unroll
        for (int i = 0; i < 4; i++) av[i] = *(const float4*)&As[mrow + i][k0];
#pragma unroll
        for (int kk = 0; kk < 4; kk++) {
            ulonglong2 bq0 = *(const ulonglong2*)&Bs[k0 + kk][ncol];
            ulonglong2 bq1 = *(const ulonglong2*)&Bs[k0 + kk][ncol + 4];
#pragma unroll
            for (int i = 0; i < 4; i++) {
                float a = (kk == 0) ? av[i].x : (kk == 1) ? av[i].y
                         : (kk == 2) ? av[i].z : av[i].w;
                unsigned long long ap;
                asm("mov.b64 %0, {%1, %1};" : "=l"(ap) : "r"(__float_as_uint(a)));
                asm("fma.rn.f32x2 %0, %1, %2, %0;" : "+l"(acc[i][0]) : "l"(ap), "l"(bq0.x));
                asm("fma.rn.f32x2 %0, %1, %2, %0;" : "+l"(acc[i][1]) : "l"(ap), "l"(bq0.y));
                asm("fma.rn.f32x2 %0, %1, %2, %0;" : "+l"(acc[i][2]) : "l"(ap), "l"(bq1.x));
                asm("fma.rn.f32x2 %0, %1, %2, %0;" : "+l"(acc[i][3]) : "l"(ap), "l"(bq1.y));
            }
        }
    }

#pragma unroll
    for (int i = 0; i < 4; i++) {
        int gm = m0 + mrow + i;
        if (gm < VOCAB) {
            ulonglong2 v0, v1;
            v0.x = acc[i][0]; v0.y = acc[i][1];
            v1.x = acc[i][2]; v1.y = acc[i][3];
            *(ulonglong2*)(P + (size_t)gm * EMB + ncol)     = v0;
            *(ulonglong2*)(P + (size_t)gm * EMB + ncol + 4) = v1;
        }
    }
}

// ---------------------------------------------------------------------------
// Attention pass: one warp per code; lane l owns columns [4l, 4l+4).
// ---------------------------------------------------------------------------
__global__ __launch_bounds__(256) void attn_kernel(const float* __restrict__ W_emb,
                                                   const float* __restrict__ b_att,
                                                   const float* __restrict__ v_att,
                                                   const void* __restrict__ leaves,
                                                   const void* __restrict__ ancestors,
                                                   float* __restrict__ out) {
    const int warp = (blockIdx.x * blockDim.x + threadIdx.x) >> 5;
    const int lane = threadIdx.x & 31;
    if (warp >= NCODES) return;
    const int c = lane * 4;
    const int is64 = g_is64;

    const float4 bv = __ldg((const float4*)(b_att + c));
    const float4 vv = __ldg((const float4*)(v_att + c));

    float s[NANC];
    int aidx[NANC];

#pragma unroll
    for (int a = 0; a < NANC; a++) {
        const size_t off = (size_t)warp * NANC + a;
        int li, ai;
        if (is64) {
            li = (int)__ldg((const long long*)leaves + off);
            ai = (int)__ldg((const long long*)ancestors + off);
        } else {
            li = __ldg((const int*)leaves + off);
            ai = __ldg((const int*)ancestors + off);
        }
        // Defensive clamp: any misinterpretation becomes a rel_err, not a crash.
        li = min(max(li, 0), VOCAB - 1);
        ai = min(max(ai, 0), VOCAB - 1);
        aidx[a] = ai;

        const float4 p1 = __ldg((const float4*)(g_P1 + (size_t)li * EMB + c));
        const float4 p2 = __ldg((const float4*)(g_P2 + (size_t)ai * EMB + c));
        const float t0 = tanh_fast(p1.x + p2.x + bv.x);
        const float t1 = tanh_fast(p1.y + p2.y + bv.y);
        const float t2 = tanh_fast(p1.z + p2.z + bv.z);
        const float t3 = tanh_fast(p1.w + p2.w + bv.w);
        float d = t0 * vv.x + t1 * vv.y + t2 * vv.z + t3 * vv.w;
        d += __shfl_xor_sync(0xffffffffu, d, 16);
        d += __shfl_xor_sync(0xffffffffu, d, 8);
        d += __shfl_xor_sync(0xffffffffu, d, 4);
        d += __shfl_xor_sync(0xffffffffu, d, 2);
        d += __shfl_xor_sync(0xffffffffu, d, 1);
        s[a] = d;
    }

    float mx = s[0];
#pragma unroll
    for (int a = 1; a < NANC; a++) mx = fmaxf(mx, s[a]);
    float e[NANC];
    float sum = 0.0f;
#pragma unroll
    for (int a = 0; a < NANC; a++) { e[a] = __expf(s[a] - mx); sum += e[a]; }
    const float inv = 1.0f / sum;

    float4 accv = make_float4(0.f, 0.f, 0.f, 0.f);
#pragma unroll
    for (int a = 0; a < NANC; a++) {
        const float w = e[a] * inv;
        const float4 em = __ldg((const float4*)(W_emb + (size_t)aidx[a] * EMB + c));
        accv.x += w * em.x;
        accv.y += w * em.y;
        accv.z += w * em.z;
        accv.w += w * em.w;
    }
    *(float4*)(out + (size_t)warp * EMB + c) = accv;
}

extern "C" void kernel_launch(void* const* d_in, const int* in_sizes, int n_in,
                              void* d_out, int out_size) {
    // Size-based input identification (robust to metadata ordering).
    const float* W_emb = nullptr;
    const float* W_att = nullptr;
    const float* b_att = nullptr;
    const float* v_att = nullptr;
    const void*  leaves = nullptr;
    const void*  ancestors = nullptr;

    for (int i = 0; i < n_in; i++) {
        const int s = in_sizes[i];
        if (s == VOCAB * EMB)            { W_emb = (const float*)d_in[i]; }
        else if (s == 2 * EMB * EMB)     { W_att = (const float*)d_in[i]; }
        else if (s == EMB)               { if (!b_att) b_att = (const float*)d_in[i];
                                           else        v_att = (const float*)d_in[i]; }
        else if (s == NCODES * NANC)     { if (!leaves) leaves = d_in[i];
                                           else         ancestors = d_in[i]; }
    }
    // Positional fallback (reference dict order) if anything is missing.
    if (!W_emb)     W_emb     = (const float*)d_in[0];
    if (!W_att)     W_att     = (const float*)d_in[1];
    if (!b_att)     b_att     = (const float*)d_in[2];
    if (!v_att)     v_att     = (const float*)d_in[3];
    if (!leaves)    leaves    = d_in[4];
    if (!ancestors) ancestors = d_in[5];

    float* out = (float*)d_out;

    detect_kernel<<<1, 1024>>>((const unsigned int*)leaves);

    const int smem_bytes = (64 * 128 + 128 * 128) * (int)sizeof(float);  // 96KB
    cudaFuncSetAttribute(proj_kernel, cudaFuncAttributeMaxDynamicSharedMemorySize, smem_bytes);

    dim3 pg((VOCAB + 63) / 64, 2);
    proj_kernel<<<pg, 256, smem_bytes>>>(W_emb, W_att);

    const int total_threads = NCODES * 32;
    attn_kernel<<<(total_threads + 255) / 256, 256>>>(W_emb, b_att, v_att,
                                                      leaves, ancestors, out);
}